// round 15
// baseline (speedup 1.0000x reference)
#include <cuda_runtime.h>
#include <cuda_bf16.h>
#include <cuda_fp16.h>
#include <math_constants.h>
#include <cstdint>

#define DIMC     384
#define NHEADS   12
#define HD       32
#define NTOK     49
#define NWIN     4096
#define MROWS    (NWIN * NTOK)   // 200704
#define QKV_N    (3 * DIMC)      // 1152
#define KDIM     384

// Scratch (device globals — no allocation allowed)
__device__ float  g_qkv[(size_t)MROWS * QKV_N];    // qkv intermediate (fp32)
__device__ __half g_xf [(size_t)MROWS * DIMC];     // x in fp16
__device__ __half g_qwf[(size_t)KDIM * QKV_N];     // qkv_w in fp16
__device__ __half g_af [(size_t)MROWS * DIMC];     // attn out in fp16
__device__ __half g_pwf[(size_t)KDIM * DIMC];      // proj_w in fp16
__device__ float  g_bias[NHEADS * NTOK * NTOK];    // expanded bias

// ---------------------------------------------------------------------------
// fp32 -> fp16 conversion (4 elems/thread)
__global__ void __launch_bounds__(256)
conv_f16(const float* __restrict__ in, __half* __restrict__ out, size_t n4)
{
    size_t i = (size_t)blockIdx.x * blockDim.x + threadIdx.x;
    if (i >= n4) return;
    float4 v = ((const float4*)in)[i];
    __half2* o = (__half2*)out;
    o[i * 2]     = __floats2half2_rn(v.x, v.y);
    o[i * 2 + 1] = __floats2half2_rn(v.z, v.w);
}

// Expand bias_table[rpi[nm]*12+h] -> g_bias[h][n][m]
__global__ void __launch_bounds__(256)
expand_bias(const float* __restrict__ bias_table, const int* __restrict__ rpi,
            float* __restrict__ out)
{
    int i = blockIdx.x * blockDim.x + threadIdx.x;
    if (i >= NHEADS * NTOK * NTOK) return;
    const int h = i / (NTOK * NTOK);
    const int nm = i - h * (NTOK * NTOK);
    out[i] = bias_table[rpi[nm] * NHEADS + h];
}

// ---------------------------------------------------------------------------
// FP16 tensor-core GEMM: C = A@B + bias (fp32 out).  (R10 winner, unchanged.)
// ---------------------------------------------------------------------------
#define AST 40
#define BST 136
#define SA_ELEMS (128 * AST)
#define SB_ELEMS (32 * BST)
#define NSTAGE 3
#define NK (KDIM / 32)   // 12
#define STAGE_F16 (SA_ELEMS + SB_ELEMS)
#define GEMM_SMEM_F16 (NSTAGE * STAGE_F16 * 2)   // 56832 B

__device__ __forceinline__ uint32_t smem_u32(const void* p) {
    return (uint32_t)__cvta_generic_to_shared(p);
}
__device__ __forceinline__ void cp16(uint32_t dst, const void* src) {
    asm volatile("cp.async.cg.shared.global [%0], [%1], 16;" :: "r"(dst), "l"(src));
}
__device__ __forceinline__ void cp_commit() { asm volatile("cp.async.commit_group;"); }
__device__ __forceinline__ void cp_wait0()  { asm volatile("cp.async.wait_group 0;"); }
__device__ __forceinline__ void cp_wait1()  { asm volatile("cp.async.wait_group 1;"); }

__device__ __forceinline__ void ldsm_x4(unsigned* r, const void* p) {
    unsigned a = smem_u32(p);
    asm volatile("ldmatrix.sync.aligned.m8n8.x4.shared.b16 {%0,%1,%2,%3}, [%4];"
        : "=r"(r[0]), "=r"(r[1]), "=r"(r[2]), "=r"(r[3]) : "r"(a));
}
__device__ __forceinline__ void ldsm_x4_t(unsigned* r, const void* p) {
    unsigned a = smem_u32(p);
    asm volatile("ldmatrix.sync.aligned.m8n8.x4.trans.shared.b16 {%0,%1,%2,%3}, [%4];"
        : "=r"(r[0]), "=r"(r[1]), "=r"(r[2]), "=r"(r[3]) : "r"(a));
}
__device__ __forceinline__ void mma_f16(float* d, const unsigned* a, const unsigned* b) {
    asm volatile(
        "mma.sync.aligned.m16n8k16.row.col.f32.f16.f16.f32 "
        "{%0,%1,%2,%3}, {%4,%5,%6,%7}, {%8,%9}, {%0,%1,%2,%3};"
        : "+f"(d[0]), "+f"(d[1]), "+f"(d[2]), "+f"(d[3])
        : "r"(a[0]), "r"(a[1]), "r"(a[2]), "r"(a[3]), "r"(b[0]), "r"(b[1]));
}

__global__ void __launch_bounds__(256, 2)
gemm_f16(const __half* __restrict__ A, const __half* __restrict__ B,
         const float* __restrict__ bias, float* __restrict__ C,
         int M, int N)
{
    extern __shared__ __half smemh[];

    const int bm = blockIdx.y * 128;
    const int bn = blockIdx.x * 128;
    const int tid  = threadIdx.x;
    const int warp = tid >> 5;
    const int lane = tid & 31;
    const int wm = (warp >> 2) * 64;
    const int wn = (warp & 3)  * 32;

    const int ar0 = tid >> 2;
    const int ac  = (tid & 3) * 8;
    const int br0 = tid >> 4;
    const int bc  = (tid & 15) * 8;

    float acc[4][4][4] = {};

    auto issue = [&](int kt, int stage) {
        __half* dA = smemh + stage * STAGE_F16;
        #pragma unroll
        for (int rr = 0; rr < 2; rr++) {
            const int r = ar0 + rr * 64;
            cp16(smem_u32(&dA[r * AST + ac]), A + (size_t)(bm + r) * KDIM + kt + ac);
        }
        __half* dB = dA + SA_ELEMS;
        #pragma unroll
        for (int rr = 0; rr < 2; rr++) {
            const int r = br0 + rr * 16;
            cp16(smem_u32(&dB[r * BST + bc]), B + (size_t)(kt + r) * N + bn + bc);
        }
    };

    issue(0, 0); cp_commit();
    issue(32, 1); cp_commit();

    #pragma unroll
    for (int it = 0; it < NK; it++) {
        const int cur = it % NSTAGE;

        if (it + 2 < NK) cp_wait1(); else cp_wait0();
        __syncthreads();
        if (it + 2 < NK) {
            issue((it + 2) * 32, (it + 2) % NSTAGE);
            cp_commit();
        }

        const __half* pA = smemh + cur * STAGE_F16;
        const __half* pB = pA + SA_ELEMS;

        #pragma unroll
        for (int ks = 0; ks < 32; ks += 16) {
            unsigned af[4][4], bf[2][4];
            const int ar  = lane & 15;
            const int akc = ks + ((lane >> 4) << 3);
            const int bkr = ks + (lane & 15);
            const int bcc = ((lane >> 4) << 3);

            #pragma unroll
            for (int mi = 0; mi < 4; mi++)
                ldsm_x4(af[mi], &pA[(wm + mi * 16 + ar) * AST + akc]);
            #pragma unroll
            for (int nb = 0; nb < 2; nb++)
                ldsm_x4_t(bf[nb], &pB[bkr * BST + wn + nb * 16 + bcc]);

            #pragma unroll
            for (int mi = 0; mi < 4; mi++)
                #pragma unroll
                for (int ni = 0; ni < 4; ni++)
                    mma_f16(acc[mi][ni], af[mi], &bf[ni >> 1][(ni & 1) * 2]);
        }
    }

    #pragma unroll
    for (int ni = 0; ni < 4; ni++) {
        const int col = bn + wn + ni * 8 + (lane & 3) * 2;
        const float bx = bias[col];
        const float by = bias[col + 1];
        #pragma unroll
        for (int mi = 0; mi < 4; mi++) {
            const int row = bm + wm + mi * 16 + (lane >> 2);
            float* a4 = acc[mi][ni];
            *(float2*)&C[(size_t)row * N + col] =
                make_float2(a4[0] + bx, a4[1] + by);
            *(float2*)&C[(size_t)(row + 8) * N + col] =
                make_float2(a4[2] + bx, a4[3] + by);
        }
    }
}

// ---------------------------------------------------------------------------
// Window attention v2: float4-vectorized smem with XOR swizzle.
// k/v element (m, d) lives at m*32 + ((d/4 ^ (m&7))*4) + d%4  -> lane-per-row
// LDS.128 is conflict-free (8 consecutive lanes cover all 32 banks).
// ---------------------------------------------------------------------------
__device__ __forceinline__ int swz(int m, int chunk) {
    return m * HD + (((chunk) ^ (m & 7)) << 2);
}

__global__ void __launch_bounds__(256)
win_attn(const float* __restrict__ qkv, const float* __restrict__ biasx,
         __half* __restrict__ outf)
{
    const int b = blockIdx.x;
    const int h = blockIdx.y;
    const int tid = threadIdx.x;

    __shared__ float qs[NTOK * HD];          // plain [49][32]
    __shared__ float ks[NTOK * HD];          // swizzled
    __shared__ float vs[NTOK * HD];          // swizzled
    __shared__ float at[NTOK][NTOK + 1];

    const float scale = 0.17677669529663687f;

    // Phase 1: load q/k/v.  warp lanes = d (conflict-free stores).
    for (int idx = tid; idx < NTOK * HD; idx += 256) {
        const int n = idx >> 5, d = idx & 31;
        const size_t base = ((size_t)b * NTOK + n) * QKV_N + h * HD + d;
        qs[n * HD + d] = qkv[base] * scale;
        const int sd = (((d >> 2) ^ (n & 7)) << 2) + (d & 3);
        ks[n * HD + sd] = qkv[base + DIMC];
        vs[n * HD + sd] = qkv[base + 2 * DIMC];
    }
    __syncthreads();

    // Phase 2: scores + bias + softmax, one warp per row n.
    const int warp = tid >> 5, lane = tid & 31;
    const float* brow_base = biasx + (size_t)h * NTOK * NTOK;
    for (int n = warp; n < NTOK; n += 8) {
        const int m2 = lane + 32;
        float v1 = 0.f, v2 = 0.f;
        #pragma unroll
        for (int j = 0; j < 8; j++) {
            const float4 q4 = *(const float4*)&qs[n * HD + j * 4];   // broadcast
            const float4 k1 = *(const float4*)&ks[swz(lane, j)];
            v1 = fmaf(q4.x, k1.x, v1);
            v1 = fmaf(q4.y, k1.y, v1);
            v1 = fmaf(q4.z, k1.z, v1);
            v1 = fmaf(q4.w, k1.w, v1);
            if (m2 < NTOK) {
                const float4 k2 = *(const float4*)&ks[swz(m2, j)];
                v2 = fmaf(q4.x, k2.x, v2);
                v2 = fmaf(q4.y, k2.y, v2);
                v2 = fmaf(q4.z, k2.z, v2);
                v2 = fmaf(q4.w, k2.w, v2);
            }
        }
        const float* brow = brow_base + n * NTOK;
        v1 += brow[lane];
        v2 = (m2 < NTOK) ? v2 + brow[m2] : -CUDART_INF_F;
        float mx = fmaxf(v1, v2);
        #pragma unroll
        for (int o = 16; o; o >>= 1) mx = fmaxf(mx, __shfl_xor_sync(0xFFFFFFFFu, mx, o));
        float e1 = __expf(v1 - mx);
        float e2 = (m2 < NTOK) ? __expf(v2 - mx) : 0.f;
        float sm = e1 + e2;
        #pragma unroll
        for (int o = 16; o; o >>= 1) sm += __shfl_xor_sync(0xFFFFFFFFu, sm, o);
        const float inv = __frcp_rn(sm);
        at[n][lane] = e1 * inv;
        if (m2 < NTOK) at[n][m2] = e2 * inv;
    }
    __syncthreads();

    // Phase 3: out = attn @ v.  Item = (n, d4): float4 of v, 4-chain ILP.
    for (int item = tid; item < NTOK * 8; item += 256) {
        const int n  = item >> 3;
        const int d4 = item & 7;
        float4 acc = make_float4(0.f, 0.f, 0.f, 0.f);
        #pragma unroll
        for (int m = 0; m < NTOK; m++) {
            const float a = at[n][m];                              // broadcast
            const float4 v = *(const float4*)&vs[swz(m, d4)];      // conflict-free
            acc.x = fmaf(a, v.x, acc.x);
            acc.y = fmaf(a, v.y, acc.y);
            acc.z = fmaf(a, v.z, acc.z);
            acc.w = fmaf(a, v.w, acc.w);
        }
        __half2 lo = __floats2half2_rn(acc.x, acc.y);
        __half2 hi = __floats2half2_rn(acc.z, acc.w);
        __half2* dst = (__half2*)&outf[((size_t)b * NTOK + n) * DIMC + h * HD + d4 * 4];
        dst[0] = lo;
        dst[1] = hi;
    }
}

// ---------------------------------------------------------------------------
extern "C" void kernel_launch(void* const* d_in, const int* in_sizes, int n_in,
                              void* d_out, int out_size)
{
    const float* x          = (const float*)d_in[0];
    const float* qkv_w      = (const float*)d_in[1];
    const float* qkv_b      = (const float*)d_in[2];
    const float* proj_w     = (const float*)d_in[3];
    const float* proj_b     = (const float*)d_in[4];
    const float* bias_table = (const float*)d_in[5];
    const int*   rpi        = (const int*)d_in[6];
    float* out = (float*)d_out;

    float *qkv, *biasx;
    __half *xf, *qwf, *af, *pwf;
    cudaGetSymbolAddress((void**)&qkv, g_qkv);
    cudaGetSymbolAddress((void**)&xf, g_xf);
    cudaGetSymbolAddress((void**)&qwf, g_qwf);
    cudaGetSymbolAddress((void**)&af, g_af);
    cudaGetSymbolAddress((void**)&pwf, g_pwf);
    cudaGetSymbolAddress((void**)&biasx, g_bias);

    cudaFuncSetAttribute(gemm_f16,
                         cudaFuncAttributeMaxDynamicSharedMemorySize, GEMM_SMEM_F16);

    // 0) conversions + bias expansion
    {
        size_t n4 = (size_t)MROWS * DIMC / 4;
        conv_f16<<<(unsigned)((n4 + 255) / 256), 256>>>(x, xf, n4);
        size_t w4 = (size_t)KDIM * QKV_N / 4;
        conv_f16<<<(unsigned)((w4 + 255) / 256), 256>>>(qkv_w, qwf, w4);
        size_t p4 = (size_t)KDIM * DIMC / 4;
        conv_f16<<<(unsigned)((p4 + 255) / 256), 256>>>(proj_w, pwf, p4);
        expand_bias<<<(NHEADS * NTOK * NTOK + 255) / 256, 256>>>(bias_table, rpi, biasx);
    }
    // 1) QKV GEMM (fp16 in, fp32 out)
    {
        dim3 grid(QKV_N / 128, MROWS / 128);
        gemm_f16<<<grid, 256, GEMM_SMEM_F16>>>(xf, qwf, qkv_b, qkv, MROWS, QKV_N);
    }
    // 2) Window attention (fp32 in, fp16 out)
    {
        dim3 grid(NWIN, NHEADS);
        win_attn<<<grid, 256>>>(qkv, biasx, af);
    }
    // 3) Proj GEMM (fp16 in, fp32 out)
    {
        dim3 grid(DIMC / 128, MROWS / 128);
        gemm_f16<<<grid, 256, GEMM_SMEM_F16>>>(af, pwf, proj_b, out, MROWS, DIMC);
    }
}

// round 16
// speedup vs baseline: 1.6684x; 1.6684x over previous
#include <cuda_runtime.h>
#include <cuda_bf16.h>
#include <cuda_fp16.h>
#include <math_constants.h>
#include <cstdint>

#define DIMC     384
#define NHEADS   12
#define HD       32
#define NTOK     49
#define NWIN     4096
#define MROWS    (NWIN * NTOK)   // 200704
#define QKV_N    (3 * DIMC)      // 1152
#define KDIM     384

// Scratch (device globals — no allocation allowed)
__device__ float  g_qkv[(size_t)MROWS * QKV_N];    // qkv intermediate (fp32)
__device__ __half g_xf [(size_t)MROWS * DIMC];     // x in fp16
__device__ __half g_qwf[(size_t)KDIM * QKV_N];     // qkv_w in fp16
__device__ __half g_af [(size_t)MROWS * DIMC];     // attn out in fp16
__device__ __half g_pwf[(size_t)KDIM * DIMC];      // proj_w in fp16
__device__ float  g_bias[NHEADS * NTOK * NTOK];    // expanded bias

// ---------------------------------------------------------------------------
// fp32 -> fp16 conversion (4 elems/thread)
__global__ void __launch_bounds__(256)
conv_f16(const float* __restrict__ in, __half* __restrict__ out, size_t n4)
{
    size_t i = (size_t)blockIdx.x * blockDim.x + threadIdx.x;
    if (i >= n4) return;
    float4 v = ((const float4*)in)[i];
    __half2* o = (__half2*)out;
    o[i * 2]     = __floats2half2_rn(v.x, v.y);
    o[i * 2 + 1] = __floats2half2_rn(v.z, v.w);
}

// Expand bias_table[rpi[nm]*12+h] -> g_bias[h][n][m]
__global__ void __launch_bounds__(256)
expand_bias(const float* __restrict__ bias_table, const int* __restrict__ rpi,
            float* __restrict__ out)
{
    int i = blockIdx.x * blockDim.x + threadIdx.x;
    if (i >= NHEADS * NTOK * NTOK) return;
    const int h = i / (NTOK * NTOK);
    const int nm = i - h * (NTOK * NTOK);
    out[i] = bias_table[rpi[nm] * NHEADS + h];
}

// ---------------------------------------------------------------------------
// Shared MMA plumbing
// ---------------------------------------------------------------------------
__device__ __forceinline__ uint32_t smem_u32(const void* p) {
    return (uint32_t)__cvta_generic_to_shared(p);
}
__device__ __forceinline__ void cp16(uint32_t dst, const void* src) {
    asm volatile("cp.async.cg.shared.global [%0], [%1], 16;" :: "r"(dst), "l"(src));
}
__device__ __forceinline__ void cp_commit() { asm volatile("cp.async.commit_group;"); }
__device__ __forceinline__ void cp_wait0()  { asm volatile("cp.async.wait_group 0;"); }
__device__ __forceinline__ void cp_wait1()  { asm volatile("cp.async.wait_group 1;"); }

__device__ __forceinline__ void ldsm_x4(unsigned* r, const void* p) {
    unsigned a = smem_u32(p);
    asm volatile("ldmatrix.sync.aligned.m8n8.x4.shared.b16 {%0,%1,%2,%3}, [%4];"
        : "=r"(r[0]), "=r"(r[1]), "=r"(r[2]), "=r"(r[3]) : "r"(a));
}
__device__ __forceinline__ void ldsm_x4_t(unsigned* r, const void* p) {
    unsigned a = smem_u32(p);
    asm volatile("ldmatrix.sync.aligned.m8n8.x4.trans.shared.b16 {%0,%1,%2,%3}, [%4];"
        : "=r"(r[0]), "=r"(r[1]), "=r"(r[2]), "=r"(r[3]) : "r"(a));
}
__device__ __forceinline__ void mma_f16(float* d, const unsigned* a, const unsigned* b) {
    asm volatile(
        "mma.sync.aligned.m16n8k16.row.col.f32.f16.f16.f32 "
        "{%0,%1,%2,%3}, {%4,%5,%6,%7}, {%8,%9}, {%0,%1,%2,%3};"
        : "+f"(d[0]), "+f"(d[1]), "+f"(d[2]), "+f"(d[3])
        : "r"(a[0]), "r"(a[1]), "r"(a[2]), "r"(a[3]), "r"(b[0]), "r"(b[1]));
}
__device__ __forceinline__ unsigned packh2(float x, float y) {
    __half2 p = __floats2half2_rn(x, y);
    return *(unsigned*)&p;
}

// ---------------------------------------------------------------------------
// FP16 tensor-core GEMM: C = A@B + bias (fp32 out).  (R10 winner, unchanged.)
// ---------------------------------------------------------------------------
#define AST 40
#define BST 136
#define SA_ELEMS (128 * AST)
#define SB_ELEMS (32 * BST)
#define NSTAGE 3
#define NK (KDIM / 32)   // 12
#define STAGE_F16 (SA_ELEMS + SB_ELEMS)
#define GEMM_SMEM_F16 (NSTAGE * STAGE_F16 * 2)   // 56832 B

__global__ void __launch_bounds__(256, 2)
gemm_f16(const __half* __restrict__ A, const __half* __restrict__ B,
         const float* __restrict__ bias, float* __restrict__ C,
         int M, int N)
{
    extern __shared__ __half smemh[];

    const int bm = blockIdx.y * 128;
    const int bn = blockIdx.x * 128;
    const int tid  = threadIdx.x;
    const int warp = tid >> 5;
    const int lane = tid & 31;
    const int wm = (warp >> 2) * 64;
    const int wn = (warp & 3)  * 32;

    const int ar0 = tid >> 2;
    const int ac  = (tid & 3) * 8;
    const int br0 = tid >> 4;
    const int bc  = (tid & 15) * 8;

    float acc[4][4][4] = {};

    auto issue = [&](int kt, int stage) {
        __half* dA = smemh + stage * STAGE_F16;
        #pragma unroll
        for (int rr = 0; rr < 2; rr++) {
            const int r = ar0 + rr * 64;
            cp16(smem_u32(&dA[r * AST + ac]), A + (size_t)(bm + r) * KDIM + kt + ac);
        }
        __half* dB = dA + SA_ELEMS;
        #pragma unroll
        for (int rr = 0; rr < 2; rr++) {
            const int r = br0 + rr * 16;
            cp16(smem_u32(&dB[r * BST + bc]), B + (size_t)(kt + r) * N + bn + bc);
        }
    };

    issue(0, 0); cp_commit();
    issue(32, 1); cp_commit();

    #pragma unroll
    for (int it = 0; it < NK; it++) {
        const int cur = it % NSTAGE;

        if (it + 2 < NK) cp_wait1(); else cp_wait0();
        __syncthreads();
        if (it + 2 < NK) {
            issue((it + 2) * 32, (it + 2) % NSTAGE);
            cp_commit();
        }

        const __half* pA = smemh + cur * STAGE_F16;
        const __half* pB = pA + SA_ELEMS;

        #pragma unroll
        for (int ks = 0; ks < 32; ks += 16) {
            unsigned af[4][4], bf[2][4];
            const int ar  = lane & 15;
            const int akc = ks + ((lane >> 4) << 3);
            const int bkr = ks + (lane & 15);
            const int bcc = ((lane >> 4) << 3);

            #pragma unroll
            for (int mi = 0; mi < 4; mi++)
                ldsm_x4(af[mi], &pA[(wm + mi * 16 + ar) * AST + akc]);
            #pragma unroll
            for (int nb = 0; nb < 2; nb++)
                ldsm_x4_t(bf[nb], &pB[bkr * BST + wn + nb * 16 + bcc]);

            #pragma unroll
            for (int mi = 0; mi < 4; mi++)
                #pragma unroll
                for (int ni = 0; ni < 4; ni++)
                    mma_f16(acc[mi][ni], af[mi], &bf[ni >> 1][(ni & 1) * 2]);
        }
    }

    #pragma unroll
    for (int ni = 0; ni < 4; ni++) {
        const int col = bn + wn + ni * 8 + (lane & 3) * 2;
        const float bx = bias[col];
        const float by = bias[col + 1];
        #pragma unroll
        for (int mi = 0; mi < 4; mi++) {
            const int row = bm + wm + mi * 16 + (lane >> 2);
            float* a4 = acc[mi][ni];
            *(float2*)&C[(size_t)row * N + col] =
                make_float2(a4[0] + bx, a4[1] + by);
            *(float2*)&C[(size_t)(row + 8) * N + col] =
                make_float2(a4[2] + bx, a4[3] + by);
        }
    }
}

// ---------------------------------------------------------------------------
// MMA window attention: block = (window, head), 4 warps, rows padded 49->64.
// QK^T and A@V on tensor cores; softmax in registers; C-frag of QK^T repacks
// directly into the A-frag of A@V.
// ---------------------------------------------------------------------------
#define QST  40   // Q smem row stride (halfs): 80B  -> 8 rows distinct 16B banks
#define KTST 72   // K^T row stride (halfs):   144B -> 8 rows distinct 16B banks
#define VST  40   // V row stride (halfs)

__global__ void __launch_bounds__(128)
win_attn(const float* __restrict__ qkv, const float* __restrict__ biasx,
         __half* __restrict__ outf)
{
    const int b   = blockIdx.x;
    const int h   = blockIdx.y;
    const int tid = threadIdx.x;

    __shared__ __align__(16) __half qs [64 * QST];   // [m=64][k=32]
    __shared__ __align__(16) __half kts[32 * KTST];  // [k=32][n=64]  (K^T)
    __shared__ __align__(16) __half vs [64 * VST];   // [k=64][n=32]  (V)
    __shared__ float bs[64 * 50];                    // bias [row][col], zero-padded

    const float scale = 0.17677669529663687f;

    // Phase 1a: q/k/v -> fp16 smem (padded rows zeroed)
    for (int idx = tid; idx < 64 * HD; idx += 128) {
        const int n = idx >> 5, d = idx & 31;
        float qv = 0.f, kv = 0.f, vv = 0.f;
        if (n < NTOK) {
            const size_t base = ((size_t)b * NTOK + n) * QKV_N + h * HD + d;
            qv = qkv[base] * scale;
            kv = qkv[base + DIMC];
            vv = qkv[base + 2 * DIMC];
        }
        qs [n * QST + d]  = __float2half(qv);
        kts[d * KTST + n] = __float2half(kv);
        vs [n * VST + d]  = __float2half(vv);
    }
    // Phase 1b: bias -> smem (single loop, zero padding, no write races)
    for (int idx = tid; idx < 64 * 50; idx += 128) {
        const int row = idx / 50, col = idx - row * 50;
        bs[idx] = (row < NTOK && col < NTOK)
                ? biasx[(size_t)h * NTOK * NTOK + row * NTOK + col] : 0.f;
    }
    __syncthreads();

    const int warp = tid >> 5, lane = tid & 31;
    const int r0 = warp * 16;             // m-tile base row
    const int qr = lane >> 2;             // row within half-tile
    const int qc = (lane & 3) * 2;        // col base within n8 tile
    const int row1 = r0 + qr, row2 = row1 + 8;

    // Q fragments (2 k-steps of 16)
    unsigned aq[2][4];
    #pragma unroll
    for (int ks2 = 0; ks2 < 2; ks2++)
        ldsm_x4(aq[ks2], &qs[(r0 + (lane & 15)) * QST + ks2 * 16 + ((lane >> 4) << 3)]);

    // Scores: c initialized with bias (+ -inf mask for key cols >= 49)
    float c[8][4];
    #pragma unroll
    for (int t = 0; t < 8; t++) {
        const int col = t * 8 + qc;
        c[t][0] = (col     < NTOK) ? bs[row1 * 50 + col]     : -1e30f;
        c[t][1] = (col + 1 < NTOK) ? bs[row1 * 50 + col + 1] : -1e30f;
        c[t][2] = (col     < NTOK) ? bs[row2 * 50 + col]     : -1e30f;
        c[t][3] = (col + 1 < NTOK) ? bs[row2 * 50 + col + 1] : -1e30f;
    }
    #pragma unroll
    for (int ks2 = 0; ks2 < 2; ks2++) {
        #pragma unroll
        for (int bt = 0; bt < 4; bt++) {
            unsigned bk[4];
            ldsm_x4_t(bk, &kts[(ks2 * 16 + (lane & 15)) * KTST
                               + bt * 16 + ((lane >> 4) << 3)]);
            mma_f16(c[bt * 2 + 0], aq[ks2], &bk[0]);
            mma_f16(c[bt * 2 + 1], aq[ks2], &bk[2]);
        }
    }

    // Softmax (rows row1 / row2 distributed across lane quads)
    float mx1 = -CUDART_INF_F, mx2 = -CUDART_INF_F;
    #pragma unroll
    for (int t = 0; t < 8; t++) {
        mx1 = fmaxf(mx1, fmaxf(c[t][0], c[t][1]));
        mx2 = fmaxf(mx2, fmaxf(c[t][2], c[t][3]));
    }
    mx1 = fmaxf(mx1, __shfl_xor_sync(0xFFFFFFFFu, mx1, 1));
    mx1 = fmaxf(mx1, __shfl_xor_sync(0xFFFFFFFFu, mx1, 2));
    mx2 = fmaxf(mx2, __shfl_xor_sync(0xFFFFFFFFu, mx2, 1));
    mx2 = fmaxf(mx2, __shfl_xor_sync(0xFFFFFFFFu, mx2, 2));
    float sm1 = 0.f, sm2 = 0.f;
    #pragma unroll
    for (int t = 0; t < 8; t++) {
        c[t][0] = __expf(c[t][0] - mx1); sm1 += c[t][0];
        c[t][1] = __expf(c[t][1] - mx1); sm1 += c[t][1];
        c[t][2] = __expf(c[t][2] - mx2); sm2 += c[t][2];
        c[t][3] = __expf(c[t][3] - mx2); sm2 += c[t][3];
    }
    sm1 += __shfl_xor_sync(0xFFFFFFFFu, sm1, 1);
    sm1 += __shfl_xor_sync(0xFFFFFFFFu, sm1, 2);
    sm2 += __shfl_xor_sync(0xFFFFFFFFu, sm2, 1);
    sm2 += __shfl_xor_sync(0xFFFFFFFFu, sm2, 2);
    const float inv1 = __frcp_rn(sm1);
    const float inv2 = __frcp_rn(sm2);

    // A@V: C-frags repack bit-exactly into A-frags (m16k16 over keys)
    float o[4][4] = {};
    #pragma unroll
    for (int k4 = 0; k4 < 4; k4++) {
        unsigned av[4];
        av[0] = packh2(c[k4 * 2][0],     c[k4 * 2][1]);
        av[1] = packh2(c[k4 * 2][2],     c[k4 * 2][3]);
        av[2] = packh2(c[k4 * 2 + 1][0], c[k4 * 2 + 1][1]);
        av[3] = packh2(c[k4 * 2 + 1][2], c[k4 * 2 + 1][3]);
        #pragma unroll
        for (int vt = 0; vt < 2; vt++) {
            unsigned bv[4];
            ldsm_x4_t(bv, &vs[(k4 * 16 + (lane & 15)) * VST
                              + vt * 16 + ((lane >> 4) << 3)]);
            mma_f16(o[vt * 2 + 0], av, &bv[0]);
            mma_f16(o[vt * 2 + 1], av, &bv[2]);
        }
    }

    // Epilogue: normalize + store fp16 (guard padded rows)
    #pragma unroll
    for (int nt = 0; nt < 4; nt++) {
        const int d0 = nt * 8 + qc;
        if (row1 < NTOK)
            *(__half2*)&outf[((size_t)b * NTOK + row1) * DIMC + h * HD + d0] =
                __floats2half2_rn(o[nt][0] * inv1, o[nt][1] * inv1);
        if (row2 < NTOK)
            *(__half2*)&outf[((size_t)b * NTOK + row2) * DIMC + h * HD + d0] =
                __floats2half2_rn(o[nt][2] * inv2, o[nt][3] * inv2);
    }
}

// ---------------------------------------------------------------------------
extern "C" void kernel_launch(void* const* d_in, const int* in_sizes, int n_in,
                              void* d_out, int out_size)
{
    const float* x          = (const float*)d_in[0];
    const float* qkv_w      = (const float*)d_in[1];
    const float* qkv_b      = (const float*)d_in[2];
    const float* proj_w     = (const float*)d_in[3];
    const float* proj_b     = (const float*)d_in[4];
    const float* bias_table = (const float*)d_in[5];
    const int*   rpi        = (const int*)d_in[6];
    float* out = (float*)d_out;

    float *qkv, *biasx;
    __half *xf, *qwf, *af, *pwf;
    cudaGetSymbolAddress((void**)&qkv, g_qkv);
    cudaGetSymbolAddress((void**)&xf, g_xf);
    cudaGetSymbolAddress((void**)&qwf, g_qwf);
    cudaGetSymbolAddress((void**)&af, g_af);
    cudaGetSymbolAddress((void**)&pwf, g_pwf);
    cudaGetSymbolAddress((void**)&biasx, g_bias);

    cudaFuncSetAttribute(gemm_f16,
                         cudaFuncAttributeMaxDynamicSharedMemorySize, GEMM_SMEM_F16);

    // 0) conversions + bias expansion
    {
        size_t n4 = (size_t)MROWS * DIMC / 4;
        conv_f16<<<(unsigned)((n4 + 255) / 256), 256>>>(x, xf, n4);
        size_t w4 = (size_t)KDIM * QKV_N / 4;
        conv_f16<<<(unsigned)((w4 + 255) / 256), 256>>>(qkv_w, qwf, w4);
        size_t p4 = (size_t)KDIM * DIMC / 4;
        conv_f16<<<(unsigned)((p4 + 255) / 256), 256>>>(proj_w, pwf, p4);
        expand_bias<<<(NHEADS * NTOK * NTOK + 255) / 256, 256>>>(bias_table, rpi, biasx);
    }
    // 1) QKV GEMM (fp16 in, fp32 out)
    {
        dim3 grid(QKV_N / 128, MROWS / 128);
        gemm_f16<<<grid, 256, GEMM_SMEM_F16>>>(xf, qwf, qkv_b, qkv, MROWS, QKV_N);
    }
    // 2) MMA window attention (fp32 in, fp16 out)
    {
        dim3 grid(NWIN, NHEADS);
        win_attn<<<grid, 128>>>(qkv, biasx, af);
    }
    // 3) Proj GEMM (fp16 in, fp32 out)
    {
        dim3 grid(DIMC / 128, MROWS / 128);
        gemm_f16<<<grid, 256, GEMM_SMEM_F16>>>(af, pwf, proj_b, out, MROWS, DIMC);
    }
}

// round 17
// speedup vs baseline: 1.8777x; 1.1255x over previous
#include <cuda_runtime.h>
#include <cuda_bf16.h>
#include <cuda_fp16.h>
#include <math_constants.h>
#include <cstdint>

#define DIMC     384
#define NHEADS   12
#define HD       32
#define NTOK     49
#define NWIN     4096
#define MROWS    (NWIN * NTOK)   // 200704
#define QKV_N    (3 * DIMC)      // 1152
#define KDIM     384

// Scratch (device globals — no allocation allowed)
__device__ __half g_qkv[(size_t)MROWS * QKV_N];    // qkv intermediate (fp16)
__device__ __half g_xf [(size_t)MROWS * DIMC];     // x in fp16
__device__ __half g_qwf[(size_t)KDIM * QKV_N];     // qkv_w in fp16
__device__ __half g_af [(size_t)MROWS * DIMC];     // attn out in fp16
__device__ __half g_pwf[(size_t)KDIM * DIMC];      // proj_w in fp16
__device__ float  g_bias[NHEADS * NTOK * NTOK];    // expanded bias

// ---------------------------------------------------------------------------
// fp32 -> fp16 conversion (4 elems/thread)
__global__ void __launch_bounds__(256)
conv_f16(const float* __restrict__ in, __half* __restrict__ out, size_t n4)
{
    size_t i = (size_t)blockIdx.x * blockDim.x + threadIdx.x;
    if (i >= n4) return;
    float4 v = ((const float4*)in)[i];
    __half2* o = (__half2*)out;
    o[i * 2]     = __floats2half2_rn(v.x, v.y);
    o[i * 2 + 1] = __floats2half2_rn(v.z, v.w);
}

// Expand bias_table[rpi[nm]*12+h] -> g_bias[h][n][m]
__global__ void __launch_bounds__(256)
expand_bias(const float* __restrict__ bias_table, const int* __restrict__ rpi,
            float* __restrict__ out)
{
    int i = blockIdx.x * blockDim.x + threadIdx.x;
    if (i >= NHEADS * NTOK * NTOK) return;
    const int h = i / (NTOK * NTOK);
    const int nm = i - h * (NTOK * NTOK);
    out[i] = bias_table[rpi[nm] * NHEADS + h];
}

// ---------------------------------------------------------------------------
// Shared MMA plumbing
// ---------------------------------------------------------------------------
__device__ __forceinline__ uint32_t smem_u32(const void* p) {
    return (uint32_t)__cvta_generic_to_shared(p);
}
__device__ __forceinline__ void cp16(uint32_t dst, const void* src) {
    asm volatile("cp.async.cg.shared.global [%0], [%1], 16;" :: "r"(dst), "l"(src));
}
__device__ __forceinline__ void cp_commit() { asm volatile("cp.async.commit_group;"); }
__device__ __forceinline__ void cp_wait0()  { asm volatile("cp.async.wait_group 0;"); }
__device__ __forceinline__ void cp_wait1()  { asm volatile("cp.async.wait_group 1;"); }

__device__ __forceinline__ void ldsm_x4(unsigned* r, const void* p) {
    unsigned a = smem_u32(p);
    asm volatile("ldmatrix.sync.aligned.m8n8.x4.shared.b16 {%0,%1,%2,%3}, [%4];"
        : "=r"(r[0]), "=r"(r[1]), "=r"(r[2]), "=r"(r[3]) : "r"(a));
}
__device__ __forceinline__ void ldsm_x4_t(unsigned* r, const void* p) {
    unsigned a = smem_u32(p);
    asm volatile("ldmatrix.sync.aligned.m8n8.x4.trans.shared.b16 {%0,%1,%2,%3}, [%4];"
        : "=r"(r[0]), "=r"(r[1]), "=r"(r[2]), "=r"(r[3]) : "r"(a));
}
__device__ __forceinline__ void mma_f16(float* d, const unsigned* a, const unsigned* b) {
    asm volatile(
        "mma.sync.aligned.m16n8k16.row.col.f32.f16.f16.f32 "
        "{%0,%1,%2,%3}, {%4,%5,%6,%7}, {%8,%9}, {%0,%1,%2,%3};"
        : "+f"(d[0]), "+f"(d[1]), "+f"(d[2]), "+f"(d[3])
        : "r"(a[0]), "r"(a[1]), "r"(a[2]), "r"(a[3]), "r"(b[0]), "r"(b[1]));
}
__device__ __forceinline__ unsigned packh2(float x, float y) {
    __half2 p = __floats2half2_rn(x, y);
    return *(unsigned*)&p;
}

// ---------------------------------------------------------------------------
// FP16 tensor-core GEMM: C = A@B + bias.  OutT in {float, __half}.
// (R10 schedule, unchanged: WAIT -> SYNC -> ISSUE -> COMPUTE.)
// ---------------------------------------------------------------------------
#define AST 40
#define BST 136
#define SA_ELEMS (128 * AST)
#define SB_ELEMS (32 * BST)
#define NSTAGE 3
#define NK (KDIM / 32)   // 12
#define STAGE_F16 (SA_ELEMS + SB_ELEMS)
#define GEMM_SMEM_F16 (NSTAGE * STAGE_F16 * 2)   // 56832 B

template <typename OutT>
__global__ void __launch_bounds__(256, 2)
gemm_f16(const __half* __restrict__ A, const __half* __restrict__ B,
         const float* __restrict__ bias, OutT* __restrict__ C,
         int M, int N)
{
    extern __shared__ __half smemh[];

    const int bm = blockIdx.y * 128;
    const int bn = blockIdx.x * 128;
    const int tid  = threadIdx.x;
    const int warp = tid >> 5;
    const int lane = tid & 31;
    const int wm = (warp >> 2) * 64;
    const int wn = (warp & 3)  * 32;

    const int ar0 = tid >> 2;
    const int ac  = (tid & 3) * 8;
    const int br0 = tid >> 4;
    const int bc  = (tid & 15) * 8;

    float acc[4][4][4] = {};

    auto issue = [&](int kt, int stage) {
        __half* dA = smemh + stage * STAGE_F16;
        #pragma unroll
        for (int rr = 0; rr < 2; rr++) {
            const int r = ar0 + rr * 64;
            cp16(smem_u32(&dA[r * AST + ac]), A + (size_t)(bm + r) * KDIM + kt + ac);
        }
        __half* dB = dA + SA_ELEMS;
        #pragma unroll
        for (int rr = 0; rr < 2; rr++) {
            const int r = br0 + rr * 16;
            cp16(smem_u32(&dB[r * BST + bc]), B + (size_t)(kt + r) * N + bn + bc);
        }
    };

    issue(0, 0); cp_commit();
    issue(32, 1); cp_commit();

    #pragma unroll
    for (int it = 0; it < NK; it++) {
        const int cur = it % NSTAGE;

        if (it + 2 < NK) cp_wait1(); else cp_wait0();
        __syncthreads();
        if (it + 2 < NK) {
            issue((it + 2) * 32, (it + 2) % NSTAGE);
            cp_commit();
        }

        const __half* pA = smemh + cur * STAGE_F16;
        const __half* pB = pA + SA_ELEMS;

        #pragma unroll
        for (int ks = 0; ks < 32; ks += 16) {
            unsigned af[4][4], bf[2][4];
            const int ar  = lane & 15;
            const int akc = ks + ((lane >> 4) << 3);
            const int bkr = ks + (lane & 15);
            const int bcc = ((lane >> 4) << 3);

            #pragma unroll
            for (int mi = 0; mi < 4; mi++)
                ldsm_x4(af[mi], &pA[(wm + mi * 16 + ar) * AST + akc]);
            #pragma unroll
            for (int nb = 0; nb < 2; nb++)
                ldsm_x4_t(bf[nb], &pB[bkr * BST + wn + nb * 16 + bcc]);

            #pragma unroll
            for (int mi = 0; mi < 4; mi++)
                #pragma unroll
                for (int ni = 0; ni < 4; ni++)
                    mma_f16(acc[mi][ni], af[mi], &bf[ni >> 1][(ni & 1) * 2]);
        }
    }

    #pragma unroll
    for (int ni = 0; ni < 4; ni++) {
        const int col = bn + wn + ni * 8 + (lane & 3) * 2;
        const float bx = bias[col];
        const float by = bias[col + 1];
        #pragma unroll
        for (int mi = 0; mi < 4; mi++) {
            const int row = bm + wm + mi * 16 + (lane >> 2);
            float* a4 = acc[mi][ni];
            if constexpr (sizeof(OutT) == 4) {
                *(float2*)&C[(size_t)row * N + col] =
                    make_float2(a4[0] + bx, a4[1] + by);
                *(float2*)&C[(size_t)(row + 8) * N + col] =
                    make_float2(a4[2] + bx, a4[3] + by);
            } else {
                *(__half2*)&C[(size_t)row * N + col] =
                    __floats2half2_rn(a4[0] + bx, a4[1] + by);
                *(__half2*)&C[(size_t)(row + 8) * N + col] =
                    __floats2half2_rn(a4[2] + bx, a4[3] + by);
            }
        }
    }
}

// ---------------------------------------------------------------------------
// MMA window attention: block = (window, head), 4 warps, rows padded 49->64.
// fp16 qkv input loaded with 16B vectors; QK^T and A@V on tensor cores.
// ---------------------------------------------------------------------------
#define QST  40   // Q smem row stride (halfs): 80B
#define KTST 72   // K^T row stride (halfs):   144B
#define VST  40   // V row stride (halfs)

__global__ void __launch_bounds__(128)
win_attn(const __half* __restrict__ qkv, const float* __restrict__ biasx,
         __half* __restrict__ outf)
{
    const int b   = blockIdx.x;
    const int h   = blockIdx.y;
    const int tid = threadIdx.x;

    __shared__ __align__(16) __half qs [64 * QST];   // [m=64][k=32]
    __shared__ __align__(16) __half kts[32 * KTST];  // [k=32][n=64]  (K^T)
    __shared__ __align__(16) __half vs [64 * VST];   // [k=64][n=32]  (V)
    __shared__ float bs[64 * 50];                    // bias, zero-padded

    const float scale = 0.17677669529663687f;

    // Phase 1a: q/k/v -> smem.  Item = (row, 8-half chunk): 16B vector loads.
    for (int idx = tid; idx < 64 * 4; idx += 128) {
        const int n  = idx >> 2;
        const int c8 = (idx & 3) * 8;
        uint4 qv = make_uint4(0, 0, 0, 0);
        uint4 kv = make_uint4(0, 0, 0, 0);
        uint4 vv = make_uint4(0, 0, 0, 0);
        if (n < NTOK) {
            const size_t base = ((size_t)b * NTOK + n) * QKV_N + h * HD + c8;
            qv = *(const uint4*)(qkv + base);
            kv = *(const uint4*)(qkv + base + DIMC);
            vv = *(const uint4*)(qkv + base + 2 * DIMC);
        }
        // scale q through fp32 round-trip
        __half2* qh = (__half2*)&qv;
        #pragma unroll
        for (int j = 0; j < 4; j++) {
            float2 f = __half22float2(qh[j]);
            qh[j] = __floats2half2_rn(f.x * scale, f.y * scale);
        }
        *(uint4*)&qs[n * QST + c8] = qv;     // n*80B + 16B*chunk: 16B aligned
        *(uint4*)&vs[n * VST + c8] = vv;
        const __half* kh = (const __half*)&kv;
        #pragma unroll
        for (int j = 0; j < 8; j++)
            kts[(c8 + j) * KTST + n] = kh[j];
    }
    // Phase 1b: bias -> smem (zero padding)
    for (int idx = tid; idx < 64 * 50; idx += 128) {
        const int row = idx / 50, col = idx - row * 50;
        bs[idx] = (row < NTOK && col < NTOK)
                ? biasx[(size_t)h * NTOK * NTOK + row * NTOK + col] : 0.f;
    }
    __syncthreads();

    const int warp = tid >> 5, lane = tid & 31;
    const int r0 = warp * 16;
    const int qr = lane >> 2;
    const int qc = (lane & 3) * 2;
    const int row1 = r0 + qr, row2 = row1 + 8;

    // Q fragments (2 k-steps of 16)
    unsigned aq[2][4];
    #pragma unroll
    for (int ks2 = 0; ks2 < 2; ks2++)
        ldsm_x4(aq[ks2], &qs[(r0 + (lane & 15)) * QST + ks2 * 16 + ((lane >> 4) << 3)]);

    // Scores: c initialized with bias (+ -inf mask for key cols >= 49)
    float c[8][4];
    #pragma unroll
    for (int t = 0; t < 8; t++) {
        const int col = t * 8 + qc;
        c[t][0] = (col     < NTOK) ? bs[row1 * 50 + col]     : -1e30f;
        c[t][1] = (col + 1 < NTOK) ? bs[row1 * 50 + col + 1] : -1e30f;
        c[t][2] = (col     < NTOK) ? bs[row2 * 50 + col]     : -1e30f;
        c[t][3] = (col + 1 < NTOK) ? bs[row2 * 50 + col + 1] : -1e30f;
    }
    #pragma unroll
    for (int ks2 = 0; ks2 < 2; ks2++) {
        #pragma unroll
        for (int bt = 0; bt < 4; bt++) {
            unsigned bk[4];
            ldsm_x4_t(bk, &kts[(ks2 * 16 + (lane & 15)) * KTST
                               + bt * 16 + ((lane >> 4) << 3)]);
            mma_f16(c[bt * 2 + 0], aq[ks2], &bk[0]);
            mma_f16(c[bt * 2 + 1], aq[ks2], &bk[2]);
        }
    }

    // Softmax (rows row1 / row2 across lane quads)
    float mx1 = -CUDART_INF_F, mx2 = -CUDART_INF_F;
    #pragma unroll
    for (int t = 0; t < 8; t++) {
        mx1 = fmaxf(mx1, fmaxf(c[t][0], c[t][1]));
        mx2 = fmaxf(mx2, fmaxf(c[t][2], c[t][3]));
    }
    mx1 = fmaxf(mx1, __shfl_xor_sync(0xFFFFFFFFu, mx1, 1));
    mx1 = fmaxf(mx1, __shfl_xor_sync(0xFFFFFFFFu, mx1, 2));
    mx2 = fmaxf(mx2, __shfl_xor_sync(0xFFFFFFFFu, mx2, 1));
    mx2 = fmaxf(mx2, __shfl_xor_sync(0xFFFFFFFFu, mx2, 2));
    float sm1 = 0.f, sm2 = 0.f;
    #pragma unroll
    for (int t = 0; t < 8; t++) {
        c[t][0] = __expf(c[t][0] - mx1); sm1 += c[t][0];
        c[t][1] = __expf(c[t][1] - mx1); sm1 += c[t][1];
        c[t][2] = __expf(c[t][2] - mx2); sm2 += c[t][2];
        c[t][3] = __expf(c[t][3] - mx2); sm2 += c[t][3];
    }
    sm1 += __shfl_xor_sync(0xFFFFFFFFu, sm1, 1);
    sm1 += __shfl_xor_sync(0xFFFFFFFFu, sm1, 2);
    sm2 += __shfl_xor_sync(0xFFFFFFFFu, sm2, 1);
    sm2 += __shfl_xor_sync(0xFFFFFFFFu, sm2, 2);
    const float inv1 = __frcp_rn(sm1);
    const float inv2 = __frcp_rn(sm2);

    // A@V: C-frags repack directly into A-frags (m16k16 over keys)
    float o[4][4] = {};
    #pragma unroll
    for (int k4 = 0; k4 < 4; k4++) {
        unsigned av[4];
        av[0] = packh2(c[k4 * 2][0],     c[k4 * 2][1]);
        av[1] = packh2(c[k4 * 2][2],     c[k4 * 2][3]);
        av[2] = packh2(c[k4 * 2 + 1][0], c[k4 * 2 + 1][1]);
        av[3] = packh2(c[k4 * 2 + 1][2], c[k4 * 2 + 1][3]);
        #pragma unroll
        for (int vt = 0; vt < 2; vt++) {
            unsigned bv[4];
            ldsm_x4_t(bv, &vs[(k4 * 16 + (lane & 15)) * VST
                              + vt * 16 + ((lane >> 4) << 3)]);
            mma_f16(o[vt * 2 + 0], av, &bv[0]);
            mma_f16(o[vt * 2 + 1], av, &bv[2]);
        }
    }

    // Epilogue: normalize + store fp16 (guard padded rows)
    #pragma unroll
    for (int nt = 0; nt < 4; nt++) {
        const int d0 = nt * 8 + qc;
        if (row1 < NTOK)
            *(__half2*)&outf[((size_t)b * NTOK + row1) * DIMC + h * HD + d0] =
                __floats2half2_rn(o[nt][0] * inv1, o[nt][1] * inv1);
        if (row2 < NTOK)
            *(__half2*)&outf[((size_t)b * NTOK + row2) * DIMC + h * HD + d0] =
                __floats2half2_rn(o[nt][2] * inv2, o[nt][3] * inv2);
    }
}

// ---------------------------------------------------------------------------
extern "C" void kernel_launch(void* const* d_in, const int* in_sizes, int n_in,
                              void* d_out, int out_size)
{
    const float* x          = (const float*)d_in[0];
    const float* qkv_w      = (const float*)d_in[1];
    const float* qkv_b      = (const float*)d_in[2];
    const float* proj_w     = (const float*)d_in[3];
    const float* proj_b     = (const float*)d_in[4];
    const float* bias_table = (const float*)d_in[5];
    const int*   rpi        = (const int*)d_in[6];
    float* out = (float*)d_out;

    float *biasx;
    __half *qkv, *xf, *qwf, *af, *pwf;
    cudaGetSymbolAddress((void**)&qkv, g_qkv);
    cudaGetSymbolAddress((void**)&xf, g_xf);
    cudaGetSymbolAddress((void**)&qwf, g_qwf);
    cudaGetSymbolAddress((void**)&af, g_af);
    cudaGetSymbolAddress((void**)&pwf, g_pwf);
    cudaGetSymbolAddress((void**)&biasx, g_bias);

    cudaFuncSetAttribute(gemm_f16<float>,
                         cudaFuncAttributeMaxDynamicSharedMemorySize, GEMM_SMEM_F16);
    cudaFuncSetAttribute(gemm_f16<__half>,
                         cudaFuncAttributeMaxDynamicSharedMemorySize, GEMM_SMEM_F16);

    // 0) conversions + bias expansion
    {
        size_t n4 = (size_t)MROWS * DIMC / 4;
        conv_f16<<<(unsigned)((n4 + 255) / 256), 256>>>(x, xf, n4);
        size_t w4 = (size_t)KDIM * QKV_N / 4;
        conv_f16<<<(unsigned)((w4 + 255) / 256), 256>>>(qkv_w, qwf, w4);
        size_t p4 = (size_t)KDIM * DIMC / 4;
        conv_f16<<<(unsigned)((p4 + 255) / 256), 256>>>(proj_w, pwf, p4);
        expand_bias<<<(NHEADS * NTOK * NTOK + 255) / 256, 256>>>(bias_table, rpi, biasx);
    }
    // 1) QKV GEMM (fp16 in, fp16 out)
    {
        dim3 grid(QKV_N / 128, MROWS / 128);
        gemm_f16<__half><<<grid, 256, GEMM_SMEM_F16>>>(xf, qwf, qkv_b, qkv,
                                                       MROWS, QKV_N);
    }
    // 2) MMA window attention (fp16 in, fp16 out)
    {
        dim3 grid(NWIN, NHEADS);
        win_attn<<<grid, 128>>>(qkv, biasx, af);
    }
    // 3) Proj GEMM (fp16 in, fp32 out)
    {
        dim3 grid(DIMC / 128, MROWS / 128);
        gemm_f16<float><<<grid, 256, GEMM_SMEM_F16>>>(af, pwf, proj_b, out,
                                                      MROWS, DIMC);
    }
}